// round 8
// baseline (speedup 1.0000x reference)
#include <cuda_runtime.h>
#include <cstdint>

// MeanAggregator: out[n,:] = mean over valid neighbors of features[idx[n,k],:]
// features: [60000,128] f32 (30.7MB, L2-resident). idx: [10000,64] (int64 or
// int32 per harness). mask: [10000,64] (byte or int32). out: [10000,128] f32.
//
// One warp per node (wave launch), lane l owns dims [4l,4l+4) as float4.
// Valid neighbor indices are warp-compacted into smem, then gathered 8 loads
// at a time (MLP=8 per warp). Pad slots alias row 0; their contribution is
// removed after the loop (one L2-hit load + FMA), keeping the hot loop one
// uniform pure-add path -> ~50 regs -> 4-5 blocks/SM for latency cover.

#define K_NEIGH 64
#define D_VEC   32
#define WARPS_PER_BLOCK 8

__device__ int g_idx_is64;
__device__ int g_mask_is32;

__global__ void detect_kernel(const int* idx_words, const unsigned char* mask_bytes)
{
    const int lane = threadIdx.x;
    // int64 idx -> all odd 32-bit words (high halves) are 0. 128 samples.
    int v = 0;
    #pragma unroll
    for (int r = 0; r < 4; r++) v |= idx_words[2 * (lane + 32 * r) + 1];
    unsigned idx_nz = __ballot_sync(0xffffffffu, v != 0);

    // int32 mask -> bytes at offset%4 != 0 are all 0. ~96 random samples.
    int m = 0;
    #pragma unroll
    for (int r = 0; r < 4; r++) {
        int p = lane + 32 * r;
        if ((p & 3) != 0) m |= mask_bytes[p];
    }
    unsigned msk_nz = __ballot_sync(0xffffffffu, m != 0);

    if (lane == 0) {
        g_idx_is64  = (idx_nz == 0) ? 1 : 0;
        g_mask_is32 = (msk_nz == 0) ? 1 : 0;
    }
}

__global__ __launch_bounds__(256) void mean_agg_kernel(
    const float4* __restrict__ feat,
    const void* __restrict__ nidx,
    const void* __restrict__ nmask,
    float4* __restrict__ out,
    int n_nodes)
{
    __shared__ int srows[WARPS_PER_BLOCK][K_NEIGH];

    const int warp  = threadIdx.x >> 5;
    const int lane  = threadIdx.x & 31;
    const int gwarp = blockIdx.x * WARPS_PER_BLOCK + warp;
    if (gwarp >= n_nodes) return;

    const size_t base = (size_t)gwarp * K_NEIGH;

    int i0, i1;
    if (g_idx_is64) {
        const long long* p = (const long long*)nidx + base;
        i0 = (int)p[lane]; i1 = (int)p[lane + 32];
    } else {
        const int* p = (const int*)nidx + base;
        i0 = p[lane]; i1 = p[lane + 32];
    }

    int m0, m1;
    if (g_mask_is32) {
        const int* p = (const int*)nmask + base;
        m0 = (p[lane] != 0); m1 = (p[lane + 32] != 0);
    } else {
        const unsigned char* p = (const unsigned char*)nmask + base;
        m0 = (p[lane] != 0); m1 = (p[lane + 32] != 0);
    }

    const unsigned b0 = __ballot_sync(0xffffffffu, m0);
    const unsigned b1 = __ballot_sync(0xffffffffu, m1);
    const int c0  = __popc(b0);
    const int cnt = c0 + __popc(b1);

    if (cnt == 0) {
        out[(size_t)gwarp * D_VEC + lane] = make_float4(0.f, 0.f, 0.f, 0.f);
        return;
    }

    // Pads alias row 0; removed after the loop.
    srows[warp][lane] = 0;
    srows[warp][lane + 32] = 0;
    __syncwarp();
    const unsigned lt = (1u << lane) - 1u;
    if (m0) srows[warp][__popc(b0 & lt)] = i0;
    if (m1) srows[warp][c0 + __popc(b1 & lt)] = i1;
    __syncwarp();

    float4 a0 = make_float4(0.f,0.f,0.f,0.f);
    float4 a1 = a0, a2 = a0, a3 = a0;

    const int cnt8 = (cnt + 7) & ~7;

    // Prefetch first chunk's indices.
    int r0 = srows[warp][0], r1 = srows[warp][1];
    int r2 = srows[warp][2], r3 = srows[warp][3];
    int r4 = srows[warp][4], r5 = srows[warp][5];
    int r6 = srows[warp][6], r7 = srows[warp][7];

    for (int j = 0; j < cnt8; j += 8) {
        // 8 independent gathers in flight per warp.
        float4 f0 = __ldg(&feat[(size_t)r0 * D_VEC + lane]);
        float4 f1 = __ldg(&feat[(size_t)r1 * D_VEC + lane]);
        float4 f2 = __ldg(&feat[(size_t)r2 * D_VEC + lane]);
        float4 f3 = __ldg(&feat[(size_t)r3 * D_VEC + lane]);
        float4 f4 = __ldg(&feat[(size_t)r4 * D_VEC + lane]);
        float4 f5 = __ldg(&feat[(size_t)r5 * D_VEC + lane]);
        float4 f6 = __ldg(&feat[(size_t)r6 * D_VEC + lane]);
        float4 f7 = __ldg(&feat[(size_t)r7 * D_VEC + lane]);

        // Prefetch next chunk's indices while the gathers are in flight.
        if (j + 8 < cnt8) {
            r0 = srows[warp][j+8],  r1 = srows[warp][j+9];
            r2 = srows[warp][j+10], r3 = srows[warp][j+11];
            r4 = srows[warp][j+12], r5 = srows[warp][j+13];
            r6 = srows[warp][j+14], r7 = srows[warp][j+15];
        }

        a0.x += f0.x; a0.y += f0.y; a0.z += f0.z; a0.w += f0.w;
        a1.x += f1.x; a1.y += f1.y; a1.z += f1.z; a1.w += f1.w;
        a2.x += f2.x; a2.y += f2.y; a2.z += f2.z; a2.w += f2.w;
        a3.x += f3.x; a3.y += f3.y; a3.z += f3.z; a3.w += f3.w;
        a0.x += f4.x; a0.y += f4.y; a0.z += f4.z; a0.w += f4.w;
        a1.x += f5.x; a1.y += f5.y; a1.z += f5.z; a1.w += f5.w;
        a2.x += f6.x; a2.y += f6.y; a2.z += f6.z; a2.w += f6.w;
        a3.x += f7.x; a3.y += f7.y; a3.z += f7.z; a3.w += f7.w;
    }

    // Remove the pad contributions (pads all read row 0).
    if (cnt8 != cnt) {
        const float npad = (float)(cnt8 - cnt);
        float4 fz = __ldg(&feat[lane]);   // row 0
        a0.x -= npad * fz.x; a0.y -= npad * fz.y;
        a0.z -= npad * fz.z; a0.w -= npad * fz.w;
    }

    const float inv = 1.0f / (float)cnt;
    float4 r;
    r.x = (a0.x + a1.x + a2.x + a3.x) * inv;
    r.y = (a0.y + a1.y + a2.y + a3.y) * inv;
    r.z = (a0.z + a1.z + a2.z + a3.z) * inv;
    r.w = (a0.w + a1.w + a2.w + a3.w) * inv;
    out[(size_t)gwarp * D_VEC + lane] = r;
}

extern "C" void kernel_launch(void* const* d_in, const int* in_sizes, int n_in,
                              void* d_out, int out_size)
{
    const float* feat  = (const float*)d_in[0];
    const void*  nidx  = d_in[1];
    const void*  nmask = d_in[2];
    float* out = (float*)d_out;

    int n_nodes = in_sizes[1] / K_NEIGH;   // 10000

    detect_kernel<<<1, 32>>>((const int*)nidx, (const unsigned char*)nmask);

    const int threads = 32 * WARPS_PER_BLOCK;
    int blocks = (n_nodes + WARPS_PER_BLOCK - 1) / WARPS_PER_BLOCK;
    mean_agg_kernel<<<blocks, threads>>>(
        (const float4*)feat, nidx, nmask, (float4*)out, n_nodes);
}

// round 9
// speedup vs baseline: 1.1167x; 1.1167x over previous
#include <cuda_runtime.h>
#include <cstdint>

// MeanAggregator: out[n,:] = mean over valid neighbors of features[idx[n,k],:]
// features: [60000,128] f32 (30.7MB, L2-resident). idx: [10000,64] (int64 or
// int32 per harness). mask: [10000,64] (byte or int32). out: [10000,128] f32.
//
// One warp per node, lane l owns dims [4l,4l+4) as float4. Valid neighbor
// indices are warp-compacted into smem, then gathered 8 loads at a time.
// The dual accumulate paths (full chunk vs weighted tail) keep all 8 loaded
// float4s live across the branch, forcing ptxas to front-batch all 8
// LDG.128s (true MLP=8) -- measured 18.0us vs 20.3us for the single-path
// variant where ptxas interleaves loads with adds. Dtype detection is
// inlined per-warp (L2-hit probes) to avoid a separate kernel launch.

#define K_NEIGH 64
#define D_VEC   32
#define WARPS_PER_BLOCK 8

__global__ __launch_bounds__(256) void mean_agg_kernel(
    const float4* __restrict__ feat,
    const void* __restrict__ nidx,
    const void* __restrict__ nmask,
    float4* __restrict__ out,
    int n_nodes)
{
    __shared__ int srows[WARPS_PER_BLOCK][K_NEIGH];

    const int warp  = threadIdx.x >> 5;
    const int lane  = threadIdx.x & 31;
    const int gwarp = blockIdx.x * WARPS_PER_BLOCK + warp;
    if (gwarp >= n_nodes) return;

    // ---- Inline dtype detection (probes hit L1/L2 after first block) ----
    // int64 idx -> all odd 32-bit words (high halves) are 0 over 128 samples.
    {
        const int* iw = (const int*)nidx;
        int v = 0;
        #pragma unroll
        for (int r = 0; r < 4; r++) v |= iw[2 * (lane + 32 * r) + 1];
        const unsigned idx_nz = __ballot_sync(0xffffffffu, v != 0);
        const int idx_is64 = (idx_nz == 0);

        // int32 mask -> bytes at offset%4 != 0 are all 0 (~96 random samples).
        const unsigned char* mb = (const unsigned char*)nmask;
        int mm = 0;
        #pragma unroll
        for (int r = 0; r < 4; r++) {
            int p = lane + 32 * r;
            if ((p & 3) != 0) mm |= mb[p];
        }
        const unsigned msk_nz = __ballot_sync(0xffffffffu, mm != 0);
        const int mask_is32 = (msk_nz == 0);

        const size_t base = (size_t)gwarp * K_NEIGH;

        int i0, i1;
        if (idx_is64) {
            const long long* p = (const long long*)nidx + base;
            i0 = (int)p[lane]; i1 = (int)p[lane + 32];
        } else {
            const int* p = (const int*)nidx + base;
            i0 = p[lane]; i1 = p[lane + 32];
        }

        int m0, m1;
        if (mask_is32) {
            const int* p = (const int*)nmask + base;
            m0 = (p[lane] != 0); m1 = (p[lane + 32] != 0);
        } else {
            const unsigned char* p = (const unsigned char*)nmask + base;
            m0 = (p[lane] != 0); m1 = (p[lane + 32] != 0);
        }

        const unsigned b0 = __ballot_sync(0xffffffffu, m0);
        const unsigned b1 = __ballot_sync(0xffffffffu, m1);
        const int c0 = __popc(b0);
        const unsigned lt = (1u << lane) - 1u;

        // Pad slots with row 0 (zeroed by tail weights).
        srows[warp][lane] = 0;
        srows[warp][lane + 32] = 0;
        __syncwarp();
        if (m0) srows[warp][__popc(b0 & lt)] = i0;
        if (m1) srows[warp][c0 + __popc(b1 & lt)] = i1;
        __syncwarp();

        const int cnt = c0 + __popc(b1);
        if (cnt == 0) {
            out[(size_t)gwarp * D_VEC + lane] = make_float4(0.f, 0.f, 0.f, 0.f);
            return;
        }

        float4 a0 = make_float4(0.f,0.f,0.f,0.f);
        float4 a1 = a0, a2 = a0, a3 = a0;

        const int cnt8 = (cnt + 7) & ~7;

        // Prefetch first chunk's indices.
        int r0 = srows[warp][0], r1 = srows[warp][1];
        int r2 = srows[warp][2], r3 = srows[warp][3];
        int r4 = srows[warp][4], r5 = srows[warp][5];
        int r6 = srows[warp][6], r7 = srows[warp][7];

        for (int j = 0; j < cnt8; j += 8) {
            // 8 independent gathers in flight per warp.
            float4 f0 = __ldg(&feat[(size_t)r0 * D_VEC + lane]);
            float4 f1 = __ldg(&feat[(size_t)r1 * D_VEC + lane]);
            float4 f2 = __ldg(&feat[(size_t)r2 * D_VEC + lane]);
            float4 f3 = __ldg(&feat[(size_t)r3 * D_VEC + lane]);
            float4 f4 = __ldg(&feat[(size_t)r4 * D_VEC + lane]);
            float4 f5 = __ldg(&feat[(size_t)r5 * D_VEC + lane]);
            float4 f6 = __ldg(&feat[(size_t)r6 * D_VEC + lane]);
            float4 f7 = __ldg(&feat[(size_t)r7 * D_VEC + lane]);

            // Prefetch next chunk's indices while the gathers are in flight.
            if (j + 8 < cnt8) {
                r0 = srows[warp][j+8],  r1 = srows[warp][j+9];
                r2 = srows[warp][j+10], r3 = srows[warp][j+11];
                r4 = srows[warp][j+12], r5 = srows[warp][j+13];
                r6 = srows[warp][j+14], r7 = srows[warp][j+15];
            }

            if (j + 8 <= cnt) {   // warp-uniform: full chunk, pure adds
                a0.x += f0.x; a0.y += f0.y; a0.z += f0.z; a0.w += f0.w;
                a1.x += f1.x; a1.y += f1.y; a1.z += f1.z; a1.w += f1.w;
                a2.x += f2.x; a2.y += f2.y; a2.z += f2.z; a2.w += f2.w;
                a3.x += f3.x; a3.y += f3.y; a3.z += f3.z; a3.w += f3.w;
                a0.x += f4.x; a0.y += f4.y; a0.z += f4.z; a0.w += f4.w;
                a1.x += f5.x; a1.y += f5.y; a1.z += f5.z; a1.w += f5.w;
                a2.x += f6.x; a2.y += f6.y; a2.z += f6.z; a2.w += f6.w;
                a3.x += f7.x; a3.y += f7.y; a3.z += f7.z; a3.w += f7.w;
            } else {              // tail chunk: weight out the pads
                float w0 = (j+0 < cnt) ? 1.f : 0.f, w1 = (j+1 < cnt) ? 1.f : 0.f;
                float w2 = (j+2 < cnt) ? 1.f : 0.f, w3 = (j+3 < cnt) ? 1.f : 0.f;
                float w4 = (j+4 < cnt) ? 1.f : 0.f, w5 = (j+5 < cnt) ? 1.f : 0.f;
                float w6 = (j+6 < cnt) ? 1.f : 0.f, w7 = (j+7 < cnt) ? 1.f : 0.f;
                a0.x += w0*f0.x; a0.y += w0*f0.y; a0.z += w0*f0.z; a0.w += w0*f0.w;
                a1.x += w1*f1.x; a1.y += w1*f1.y; a1.z += w1*f1.z; a1.w += w1*f1.w;
                a2.x += w2*f2.x; a2.y += w2*f2.y; a2.z += w2*f2.z; a2.w += w2*f2.w;
                a3.x += w3*f3.x; a3.y += w3*f3.y; a3.z += w3*f3.z; a3.w += w3*f3.w;
                a0.x += w4*f4.x; a0.y += w4*f4.y; a0.z += w4*f4.z; a0.w += w4*f4.w;
                a1.x += w5*f5.x; a1.y += w5*f5.y; a1.z += w5*f5.z; a1.w += w5*f5.w;
                a2.x += w6*f6.x; a2.y += w6*f6.y; a2.z += w6*f6.z; a2.w += w6*f6.w;
                a3.x += w7*f7.x; a3.y += w7*f7.y; a3.z += w7*f7.z; a3.w += w7*f7.w;
            }
        }

        const float inv = 1.0f / (float)cnt;
        float4 r;
        r.x = (a0.x + a1.x + a2.x + a3.x) * inv;
        r.y = (a0.y + a1.y + a2.y + a3.y) * inv;
        r.z = (a0.z + a1.z + a2.z + a3.z) * inv;
        r.w = (a0.w + a1.w + a2.w + a3.w) * inv;
        out[(size_t)gwarp * D_VEC + lane] = r;
    }
}

extern "C" void kernel_launch(void* const* d_in, const int* in_sizes, int n_in,
                              void* d_out, int out_size)
{
    const float* feat  = (const float*)d_in[0];
    const void*  nidx  = d_in[1];
    const void*  nmask = d_in[2];
    float* out = (float*)d_out;

    int n_nodes = in_sizes[1] / K_NEIGH;   // 10000

    const int threads = 32 * WARPS_PER_BLOCK;
    int blocks = (n_nodes + WARPS_PER_BLOCK - 1) / WARPS_PER_BLOCK;
    mean_agg_kernel<<<blocks, threads>>>(
        (const float4*)feat, nidx, nmask, (float4*)out, n_nodes);
}